// round 13
// baseline (speedup 1.0000x reference)
#include <cuda_runtime.h>
#include <cstdint>

// ---------------------------------------------------------------------------
// GeometricPositionalFingerprinter — FINAL design (R9/R12) + __ldcs
// evict-first streaming loads (input is read exactly once; zero L2 reuse).
//
// Input : pentachora [V, 5, 128] f32  (V = in_sizes[0]/640)
// Output: cantor fingerprint [V] f32
//
// CTA = 256 threads = 8 warps, 28 pentachora per CTA.
//  - Warps 0..6 (producers): 4 pentachora each, 8 lanes/pentachoron, full
//    128B-line float4 __ldcs loads, 10 pairwise-distance accumulators,
//    3-level butterfly, SMEM stats store. No transcendental tail.
//  - Warp 7 (consumer): after __syncthreads, threads 0..27 each run the
//    scalar epilogue (edges / volume via distance-Gram det / spread via
//    centroid identity / seed / Cantor) and store out[g].
// Producers exit right after the barrier; consumers overlap with the other
// 5 resident CTAs' streaming warps. Measured (R12): 98.8 us, DRAM 86.6%,
// rel_err 7.106691e-5. This round changes ONLY the load cache policy.
// ---------------------------------------------------------------------------

static constexpr int PENT_PER_CTA = 28;   // 7 producer warps * 4 groups

__device__ __forceinline__ float sigmoid_pos(float x) {
    // x >= 0 always. ~2 ulp regardless of fast-math flags.
    if (x > 18.0f) return 1.0f;
    float t = -x;
    float kf = rintf(t * 1.4426950408889634f);
    float r = fmaf(-kf, 0.693145751953125f, t);
    r = fmaf(-kf, 1.428606765330187e-06f, r);
    float p = fmaf(r, 1.38888889e-3f, 8.33333333e-3f);
    p = fmaf(r, p, 4.16666667e-2f);
    p = fmaf(r, p, 1.66666667e-1f);
    p = fmaf(r, p, 0.5f);
    p = fmaf(r, p, 1.0f);
    p = fmaf(r, p, 1.0f);
    int ki = (int)kf;
    float scale = __int_as_float((ki + 127) << 23);
    float e = p * scale;
    return __fdiv_rn(1.0f, __fadd_rn(1.0f, e));
}

// Epilogue from the 10 reduced pairwise squared distances (triu(5,k=1)).
// Op-for-op identical to R6/R9/R12.
__device__ __forceinline__ float gpf_epilogue(const float ed[10]) {
    float e[10];
#pragma unroll
    for (int i = 0; i < 10; ++i) e[i] = __fsqrt_rn(fmaxf(ed[i], 0.0f));
    float esum = 0.0f;
#pragma unroll
    for (int i = 0; i < 10; ++i) esum = __fadd_rn(esum, e[i]);
    float mean_edge = __fdiv_rn(esum, 10.0f);
    float ess = 0.0f;
#pragma unroll
    for (int i = 0; i < 10; ++i) {
        float d = __fsub_rn(e[i], mean_edge);
        ess = fmaf(d, d, ess);
    }
    float std_edge = __fsqrt_rn(__fdiv_rn(ess, 9.0f));   // ddof=1
    float ratio = __fdiv_rn(std_edge, __fadd_rn(mean_edge, 1e-6f));

    // Vertex spread via centroid identity: cd[v] = (5*S_v - T)/25
    float T = __fadd_rn(__fadd_rn(__fadd_rn(__fadd_rn(ed[0], ed[1]),
                                            __fadd_rn(ed[2], ed[3])),
                                  __fadd_rn(__fadd_rn(ed[4], ed[5]),
                                            __fadd_rn(ed[6], ed[7]))),
                        __fadd_rn(ed[8], ed[9]));
    float S0 = __fadd_rn(__fadd_rn(ed[0], ed[1]), __fadd_rn(ed[2], ed[3]));
    float S1 = __fadd_rn(__fadd_rn(ed[0], ed[4]), __fadd_rn(ed[5], ed[6]));
    float S2 = __fadd_rn(__fadd_rn(ed[1], ed[4]), __fadd_rn(ed[7], ed[8]));
    float S3 = __fadd_rn(__fadd_rn(ed[2], ed[5]), __fadd_rn(ed[7], ed[9]));
    float S4 = __fadd_rn(__fadd_rn(ed[3], ed[6]), __fadd_rn(ed[8], ed[9]));

    float dc[5];
    float Sv[5] = { S0, S1, S2, S3, S4 };
    float csum = 0.0f;
#pragma unroll
    for (int v = 0; v < 5; ++v) {
        float cdv = __fmul_rn(__fsub_rn(__fmul_rn(5.0f, Sv[v]), T), 0.04f);
        dc[v] = __fsqrt_rn(fmaxf(cdv, 0.0f));
        csum = __fadd_rn(csum, dc[v]);
    }
    float cmean = __fdiv_rn(csum, 5.0f);
    float css = 0.0f;
#pragma unroll
    for (int v = 0; v < 5; ++v) {
        float d = __fsub_rn(dc[v], cmean);
        css = fmaf(d, d, css);
    }
    float spread = __fsqrt_rn(__fdiv_rn(css, 4.0f));

    // Volume via 4x4 edge-vector Gram det; sigmoid(10*vol) saturates to 1.0f.
    float d0[4] = { ed[0], ed[1], ed[2], ed[3] };
    float G[4][4];
#pragma unroll
    for (int i = 0; i < 4; ++i) G[i][i] = d0[i];
    G[0][1] = G[1][0] = 0.5f * ((d0[0] + d0[1]) - ed[4]);
    G[0][2] = G[2][0] = 0.5f * ((d0[0] + d0[2]) - ed[5]);
    G[0][3] = G[3][0] = 0.5f * ((d0[0] + d0[3]) - ed[6]);
    G[1][2] = G[2][1] = 0.5f * ((d0[1] + d0[2]) - ed[7]);
    G[1][3] = G[3][1] = 0.5f * ((d0[1] + d0[3]) - ed[8]);
    G[2][3] = G[3][2] = 0.5f * ((d0[2] + d0[3]) - ed[9]);

    float d2233 = G[2][2] * G[3][3] - G[2][3] * G[3][2];
    float d2133 = G[2][1] * G[3][3] - G[2][3] * G[3][1];
    float d2132 = G[2][1] * G[3][2] - G[2][2] * G[3][1];
    float d2033 = G[2][0] * G[3][3] - G[2][3] * G[3][0];
    float d2032 = G[2][0] * G[3][2] - G[2][2] * G[3][0];
    float d2031 = G[2][0] * G[3][1] - G[2][1] * G[3][0];
    float c0 = G[1][1] * d2233 - G[1][2] * d2133 + G[1][3] * d2132;
    float c1 = G[1][0] * d2233 - G[1][2] * d2033 + G[1][3] * d2032;
    float c2 = G[1][0] * d2133 - G[1][1] * d2033 + G[1][3] * d2031;
    float c3 = G[1][0] * d2132 - G[1][1] * d2032 + G[1][2] * d2031;
    float det = G[0][0] * c0 - G[0][1] * c1 + G[0][2] * c2 - G[0][3] * c3;
    float vol = __fsqrt_rn(fmaxf(__fdiv_rn(det, 576.0f), 0.0f));

    float s1 = sigmoid_pos(__fmul_rn(vol, 10.0f));
    float s2 = sigmoid_pos(ratio);
    float s3 = sigmoid_pos(spread);
    float seed = __fadd_rn(__fadd_rn(__fmul_rn(s1, 0.4f), __fmul_rn(s2, 0.3f)),
                           __fmul_rn(s3, 0.3f));

    float x = fminf(fmaxf(seed, 1e-6f), 0.999999f);

    float cantor = 0.0f;
    float factor = 0.5f;
#pragma unroll
    for (int it = 0; it < 8; ++it) {
        float xs = __fmul_rn(x, 3.0f);
        int d = (int)xs;
        x = __fsub_rn(xs, (float)d);
        if (d == 2) cantor = __fadd_rn(cantor, factor);
        factor *= 0.5f;
    }
    return fminf(fmaxf(cantor, 0.0f), 1.0f);
}

__global__ void __launch_bounds__(256, 6)
gpf_ws_kernel(const float* __restrict__ pent, float* __restrict__ out, int V)
{
    __shared__ float sed[PENT_PER_CTA][12];   // 10 stats + pad

    const int tid  = threadIdx.x;
    const int wid  = tid >> 5;                // warp id 0..7
    const int lane = tid & 31;

    if (wid < 7) {
        // ---------------- producer: stream 4 pentachora ----------------
        const int p = wid * 4 + (lane >> 3);  // group within CTA, 0..27
        const int l = lane & 7;               // lane within 8-lane group
        const int g = blockIdx.x * PENT_PER_CTA + p;

        if (g < V) {
            const float4* __restrict__ base =
                reinterpret_cast<const float4*>(pent) + (size_t)g * 160 + l;

            float ed[10];
#pragma unroll
            for (int i = 0; i < 10; ++i) ed[i] = 0.0f;

#pragma unroll
            for (int c = 0; c < 4; ++c) {
                float4 a[5];
#pragma unroll
                for (int v = 0; v < 5; ++v)
                    a[v] = __ldcs(base + v * 32 + c * 8);   // evict-first

                int m = 0;
#pragma unroll
                for (int i = 0; i < 5; ++i) {
#pragma unroll
                    for (int j = i + 1; j < 5; ++j) {
                        float dx = a[i].x - a[j].x;
                        float dy = a[i].y - a[j].y;
                        float dz = a[i].z - a[j].z;
                        float dw = a[i].w - a[j].w;
                        float t = ed[m];
                        t = fmaf(dx, dx, t);
                        t = fmaf(dy, dy, t);
                        t = fmaf(dz, dz, t);
                        t = fmaf(dw, dw, t);
                        ed[m] = t;
                        ++m;
                    }
                }
            }

            // 3-level butterfly across the 8-lane group
#pragma unroll
            for (int i = 0; i < 10; ++i) {
                ed[i] += __shfl_xor_sync(0xffffffffu, ed[i], 1);
                ed[i] += __shfl_xor_sync(0xffffffffu, ed[i], 2);
                ed[i] += __shfl_xor_sync(0xffffffffu, ed[i], 4);
            }

            // Lane l stores ed[l]; lanes 0,1 also store ed[8],ed[9].
            float v = ed[0];
            if (l == 1) v = ed[1];
            if (l == 2) v = ed[2];
            if (l == 3) v = ed[3];
            if (l == 4) v = ed[4];
            if (l == 5) v = ed[5];
            if (l == 6) v = ed[6];
            if (l == 7) v = ed[7];
            sed[p][l] = v;
            if (l < 2) sed[p][8 + l] = (l == 0) ? ed[8] : ed[9];
        }

        __syncthreads();
        // producers exit here
    } else {
        // ---------------- consumer: 28 epilogues ----------------
        __syncthreads();

        if (lane < PENT_PER_CTA) {
            int g = blockIdx.x * PENT_PER_CTA + lane;
            if (g < V) {
                float ed[10];
#pragma unroll
                for (int i = 0; i < 10; ++i) ed[i] = sed[lane][i];
                out[g] = gpf_epilogue(ed);
            }
        }
    }
}

extern "C" void kernel_launch(void* const* d_in, const int* in_sizes, int n_in,
                              void* d_out, int out_size)
{
    const float* p = (const float*)d_in[0];
    float* out = (float*)d_out;
    int V = in_sizes[0] / 640;                 // [V, 5, 128]
    int blocks = (V + PENT_PER_CTA - 1) / PENT_PER_CTA;
    gpf_ws_kernel<<<blocks, 256>>>(p, out, V);
}

// round 14
// speedup vs baseline: 1.0236x; 1.0236x over previous
#include <cuda_runtime.h>
#include <cstdint>

// ---------------------------------------------------------------------------
// GeometricPositionalFingerprinter — FINAL (R12 verbatim; best measured:
// 98.8 us, DRAM 86.6% / 6.86 TB/s, rel_err 7.106691e-5).
//
// Input : pentachora [V, 5, 128] f32  (V = in_sizes[0]/640)
// Output: cantor fingerprint [V] f32
//
// CTA = 256 threads = 8 warps, 28 pentachora per CTA.
//  - Warps 0..6 (producers): 4 pentachora each, 8 lanes/pentachoron, full
//    128B-line float4 loads, 10 pairwise-distance accumulators (40 regs ->
//    measured optimum of warps x per-warp-MLP), 3-level butterfly, SMEM
//    stats store. No transcendental tail in streaming warps.
//  - Warp 7 (consumer): after __syncthreads, threads 0..27 each run the
//    scalar epilogue (edges / volume via distance-Gram det / spread via
//    centroid identity / seed / Cantor) and store out[g].
// Producers exit right after the barrier; consumers overlap with the other
// 5 resident CTAs' streaming warps.
// ---------------------------------------------------------------------------

static constexpr int PENT_PER_CTA = 28;   // 7 producer warps * 4 groups

__device__ __forceinline__ float sigmoid_pos(float x) {
    // x >= 0 always. ~2 ulp regardless of fast-math flags.
    if (x > 18.0f) return 1.0f;
    float t = -x;
    float kf = rintf(t * 1.4426950408889634f);
    float r = fmaf(-kf, 0.693145751953125f, t);
    r = fmaf(-kf, 1.428606765330187e-06f, r);
    float p = fmaf(r, 1.38888889e-3f, 8.33333333e-3f);
    p = fmaf(r, p, 4.16666667e-2f);
    p = fmaf(r, p, 1.66666667e-1f);
    p = fmaf(r, p, 0.5f);
    p = fmaf(r, p, 1.0f);
    p = fmaf(r, p, 1.0f);
    int ki = (int)kf;
    float scale = __int_as_float((ki + 127) << 23);
    float e = p * scale;
    return __fdiv_rn(1.0f, __fadd_rn(1.0f, e));
}

// Epilogue from the 10 reduced pairwise squared distances (triu(5,k=1)).
__device__ __forceinline__ float gpf_epilogue(const float ed[10]) {
    float e[10];
#pragma unroll
    for (int i = 0; i < 10; ++i) e[i] = __fsqrt_rn(fmaxf(ed[i], 0.0f));
    float esum = 0.0f;
#pragma unroll
    for (int i = 0; i < 10; ++i) esum = __fadd_rn(esum, e[i]);
    float mean_edge = __fdiv_rn(esum, 10.0f);
    float ess = 0.0f;
#pragma unroll
    for (int i = 0; i < 10; ++i) {
        float d = __fsub_rn(e[i], mean_edge);
        ess = fmaf(d, d, ess);
    }
    float std_edge = __fsqrt_rn(__fdiv_rn(ess, 9.0f));   // ddof=1
    float ratio = __fdiv_rn(std_edge, __fadd_rn(mean_edge, 1e-6f));

    // Vertex spread via centroid identity: cd[v] = (5*S_v - T)/25
    float T = __fadd_rn(__fadd_rn(__fadd_rn(__fadd_rn(ed[0], ed[1]),
                                            __fadd_rn(ed[2], ed[3])),
                                  __fadd_rn(__fadd_rn(ed[4], ed[5]),
                                            __fadd_rn(ed[6], ed[7]))),
                        __fadd_rn(ed[8], ed[9]));
    float S0 = __fadd_rn(__fadd_rn(ed[0], ed[1]), __fadd_rn(ed[2], ed[3]));
    float S1 = __fadd_rn(__fadd_rn(ed[0], ed[4]), __fadd_rn(ed[5], ed[6]));
    float S2 = __fadd_rn(__fadd_rn(ed[1], ed[4]), __fadd_rn(ed[7], ed[8]));
    float S3 = __fadd_rn(__fadd_rn(ed[2], ed[5]), __fadd_rn(ed[7], ed[9]));
    float S4 = __fadd_rn(__fadd_rn(ed[3], ed[6]), __fadd_rn(ed[8], ed[9]));

    float dc[5];
    float Sv[5] = { S0, S1, S2, S3, S4 };
    float csum = 0.0f;
#pragma unroll
    for (int v = 0; v < 5; ++v) {
        float cdv = __fmul_rn(__fsub_rn(__fmul_rn(5.0f, Sv[v]), T), 0.04f);
        dc[v] = __fsqrt_rn(fmaxf(cdv, 0.0f));
        csum = __fadd_rn(csum, dc[v]);
    }
    float cmean = __fdiv_rn(csum, 5.0f);
    float css = 0.0f;
#pragma unroll
    for (int v = 0; v < 5; ++v) {
        float d = __fsub_rn(dc[v], cmean);
        css = fmaf(d, d, css);
    }
    float spread = __fsqrt_rn(__fdiv_rn(css, 4.0f));

    // Volume via 4x4 edge-vector Gram det; sigmoid(10*vol) saturates to 1.0f.
    float d0[4] = { ed[0], ed[1], ed[2], ed[3] };
    float G[4][4];
#pragma unroll
    for (int i = 0; i < 4; ++i) G[i][i] = d0[i];
    G[0][1] = G[1][0] = 0.5f * ((d0[0] + d0[1]) - ed[4]);
    G[0][2] = G[2][0] = 0.5f * ((d0[0] + d0[2]) - ed[5]);
    G[0][3] = G[3][0] = 0.5f * ((d0[0] + d0[3]) - ed[6]);
    G[1][2] = G[2][1] = 0.5f * ((d0[1] + d0[2]) - ed[7]);
    G[1][3] = G[3][1] = 0.5f * ((d0[1] + d0[3]) - ed[8]);
    G[2][3] = G[3][2] = 0.5f * ((d0[2] + d0[3]) - ed[9]);

    float d2233 = G[2][2] * G[3][3] - G[2][3] * G[3][2];
    float d2133 = G[2][1] * G[3][3] - G[2][3] * G[3][1];
    float d2132 = G[2][1] * G[3][2] - G[2][2] * G[3][1];
    float d2033 = G[2][0] * G[3][3] - G[2][3] * G[3][0];
    float d2032 = G[2][0] * G[3][2] - G[2][2] * G[3][0];
    float d2031 = G[2][0] * G[3][1] - G[2][1] * G[3][0];
    float c0 = G[1][1] * d2233 - G[1][2] * d2133 + G[1][3] * d2132;
    float c1 = G[1][0] * d2233 - G[1][2] * d2033 + G[1][3] * d2032;
    float c2 = G[1][0] * d2133 - G[1][1] * d2033 + G[1][3] * d2031;
    float c3 = G[1][0] * d2132 - G[1][1] * d2032 + G[1][2] * d2031;
    float det = G[0][0] * c0 - G[0][1] * c1 + G[0][2] * c2 - G[0][3] * c3;
    float vol = __fsqrt_rn(fmaxf(__fdiv_rn(det, 576.0f), 0.0f));

    float s1 = sigmoid_pos(__fmul_rn(vol, 10.0f));
    float s2 = sigmoid_pos(ratio);
    float s3 = sigmoid_pos(spread);
    float seed = __fadd_rn(__fadd_rn(__fmul_rn(s1, 0.4f), __fmul_rn(s2, 0.3f)),
                           __fmul_rn(s3, 0.3f));

    float x = fminf(fmaxf(seed, 1e-6f), 0.999999f);

    float cantor = 0.0f;
    float factor = 0.5f;
#pragma unroll
    for (int it = 0; it < 8; ++it) {
        float xs = __fmul_rn(x, 3.0f);
        int d = (int)xs;
        x = __fsub_rn(xs, (float)d);
        if (d == 2) cantor = __fadd_rn(cantor, factor);
        factor *= 0.5f;
    }
    return fminf(fmaxf(cantor, 0.0f), 1.0f);
}

__global__ void __launch_bounds__(256, 6)
gpf_ws_kernel(const float* __restrict__ pent, float* __restrict__ out, int V)
{
    __shared__ float sed[PENT_PER_CTA][12];   // 10 stats + pad

    const int tid  = threadIdx.x;
    const int wid  = tid >> 5;                // warp id 0..7
    const int lane = tid & 31;

    if (wid < 7) {
        // ---------------- producer: stream 4 pentachora ----------------
        const int p = wid * 4 + (lane >> 3);  // group within CTA, 0..27
        const int l = lane & 7;               // lane within 8-lane group
        const int g = blockIdx.x * PENT_PER_CTA + p;

        if (g < V) {
            const float4* __restrict__ base =
                reinterpret_cast<const float4*>(pent) + (size_t)g * 160 + l;

            float ed[10];
#pragma unroll
            for (int i = 0; i < 10; ++i) ed[i] = 0.0f;

#pragma unroll
            for (int c = 0; c < 4; ++c) {
                float4 a[5];
#pragma unroll
                for (int v = 0; v < 5; ++v) a[v] = base[v * 32 + c * 8];

                int m = 0;
#pragma unroll
                for (int i = 0; i < 5; ++i) {
#pragma unroll
                    for (int j = i + 1; j < 5; ++j) {
                        float dx = a[i].x - a[j].x;
                        float dy = a[i].y - a[j].y;
                        float dz = a[i].z - a[j].z;
                        float dw = a[i].w - a[j].w;
                        float t = ed[m];
                        t = fmaf(dx, dx, t);
                        t = fmaf(dy, dy, t);
                        t = fmaf(dz, dz, t);
                        t = fmaf(dw, dw, t);
                        ed[m] = t;
                        ++m;
                    }
                }
            }

            // 3-level butterfly across the 8-lane group
#pragma unroll
            for (int i = 0; i < 10; ++i) {
                ed[i] += __shfl_xor_sync(0xffffffffu, ed[i], 1);
                ed[i] += __shfl_xor_sync(0xffffffffu, ed[i], 2);
                ed[i] += __shfl_xor_sync(0xffffffffu, ed[i], 4);
            }

            // Lane l stores ed[l]; lanes 0,1 also store ed[8],ed[9].
            float v = ed[0];
            if (l == 1) v = ed[1];
            if (l == 2) v = ed[2];
            if (l == 3) v = ed[3];
            if (l == 4) v = ed[4];
            if (l == 5) v = ed[5];
            if (l == 6) v = ed[6];
            if (l == 7) v = ed[7];
            sed[p][l] = v;
            if (l < 2) sed[p][8 + l] = (l == 0) ? ed[8] : ed[9];
        }

        __syncthreads();
        // producers exit here
    } else {
        // ---------------- consumer: 28 epilogues ----------------
        __syncthreads();

        if (lane < PENT_PER_CTA) {
            int g = blockIdx.x * PENT_PER_CTA + lane;
            if (g < V) {
                float ed[10];
#pragma unroll
                for (int i = 0; i < 10; ++i) ed[i] = sed[lane][i];
                out[g] = gpf_epilogue(ed);
            }
        }
    }
}

extern "C" void kernel_launch(void* const* d_in, const int* in_sizes, int n_in,
                              void* d_out, int out_size)
{
    const float* p = (const float*)d_in[0];
    float* out = (float*)d_out;
    int V = in_sizes[0] / 640;                 // [V, 5, 128]
    int blocks = (V + PENT_PER_CTA - 1) / PENT_PER_CTA;
    gpf_ws_kernel<<<blocks, 256>>>(p, out, V);
}